// round 1
// baseline (speedup 1.0000x reference)
#include <cuda_runtime.h>
#include <cstdint>

#define T_LEN   8192
#define L_WIN   64
#define TP_LEN  (T_LEN - L_WIN + 1)   // 8129
#define P_NUM   64
#define BS      32
#define TILE_T  256
#define PAD_LEFT 32
#define EPS     1e-6f

// scratch: z-normalized shapelets, transposed [l][p], plus s2[p]
__device__ float g_sTn[L_WIN * P_NUM];
__device__ float g_s2[P_NUM];

// ---------------------------------------------------------------------------
// Prep: z-normalize shapelets (per p over L), write transposed + s2
// ---------------------------------------------------------------------------
__global__ void prep_shapelets(const float* __restrict__ sh) {
    int p = threadIdx.x;          // 64 threads
    const float* row = sh + p * L_WIN;
    float s1 = 0.f, sq = 0.f;
    #pragma unroll
    for (int l = 0; l < L_WIN; l++) { float v = row[l]; s1 += v; sq = fmaf(v, v, sq); }
    float mu  = s1 * (1.f / L_WIN);
    float var = fmaxf(sq * (1.f / L_WIN) - mu * mu, 0.f);
    float sd  = sqrtf(var);
    float inv = 1.f / fmaxf(sd, EPS);
    float sum2 = 0.f;
    #pragma unroll
    for (int l = 0; l < L_WIN; l++) {
        float sn = (row[l] - mu) * inv;
        g_sTn[l * P_NUM + p] = sn;
        sum2 = fmaf(sn, sn, sum2);
    }
    g_s2[p] = sum2;
}

// ---------------------------------------------------------------------------
// Zero the padded rows: tout in [0,32) and [Tp+32, 8192)
// ---------------------------------------------------------------------------
__global__ void pad_zero(float* __restrict__ out) {
    int idx = blockIdx.x * 256 + threadIdx.x;    // 32 * 63 * 64 = 129024
    if (idx >= BS * 63 * P_NUM) return;
    int p = idx & 63;
    int r = (idx >> 6) % 63;
    int b = idx / (63 * P_NUM);
    int tout = (r < PAD_LEFT) ? r : (TP_LEN + PAD_LEFT + (r - PAD_LEFT));
    out[((size_t)b * T_LEN + tout) * P_NUM + p] = 0.f;
}

// packed f32x2 fma
#define FMA2(d, a, b) \
    asm("fma.rn.f32x2 %0, %1, %2, %3;" : "=l"(d) : "l"(a), "l"(b), "l"(d))

// ---------------------------------------------------------------------------
// Main kernel: block = (256 windows) x (64 shapelets) for one batch b.
// Thread = 8 t's x 8 p's; packed f32x2 over p-pairs; x held in a register
// shift-ring of {x,x} pairs so only 1 LDS.64 + 2 LDS.128 per l per thread.
// ---------------------------------------------------------------------------
__global__ void __launch_bounds__(256)
shapelet_kernel(const float* __restrict__ x, float* __restrict__ out) {
    __shared__ float4 sT4[L_WIN * (P_NUM / 4)];     // 16 KB: sT[l][p]
    __shared__ float2 xs2[TILE_T + 64];             // packed {x,x}
    __shared__ float  invs[TILE_T];
    __shared__ float  w2s[TILE_T];
    __shared__ float  s2s[P_NUM];

    const int tid    = threadIdx.x;
    const int b      = blockIdx.y;
    const int t_base = blockIdx.x * TILE_T;

    // load transposed shapelets into shared
    const float4* g4 = reinterpret_cast<const float4*>(g_sTn);
    #pragma unroll
    for (int i = 0; i < 4; i++) sT4[tid + 256 * i] = g4[tid + 256 * i];
    if (tid < P_NUM) s2s[tid] = g_s2[tid];

    // load x segment (zero beyond T), packed {v,v}
    const float* xb = x + (size_t)b * T_LEN;
    {
        int idx = t_base + tid;
        float v = (idx < T_LEN) ? xb[idx] : 0.f;
        xs2[tid] = make_float2(v, v);
        if (tid < 64) {
            int idx2 = t_base + 256 + tid;
            float v2 = (idx2 < T_LEN) ? xb[idx2] : 0.f;
            xs2[256 + tid] = make_float2(v2, v2);
        }
    }
    __syncthreads();

    // per-window stats: thread tid handles local window tid
    {
        float s1 = 0.f, sq = 0.f;
        #pragma unroll
        for (int l = 0; l < L_WIN; l++) {
            float v = xs2[tid + l].x;
            s1 += v; sq = fmaf(v, v, sq);
        }
        float mu  = s1 * (1.f / L_WIN);
        float var = fmaxf(sq * (1.f / L_WIN) - mu * mu, 0.f);
        float sd  = sqrtf(var);
        float inv = 1.f / fmaxf(sd, EPS);
        invs[tid] = inv;
        w2s[tid]  = var * inv * inv * (float)L_WIN;
    }
    __syncthreads();

    const int p0 = (tid & 7) * 8;          // shapelet group
    const int tg = (tid >> 3) * 8;         // local window group (8 windows)

    const unsigned long long* xsu =
        reinterpret_cast<const unsigned long long*>(xs2);

    unsigned long long acc[8][4];
    #pragma unroll
    for (int i = 0; i < 8; i++)
        #pragma unroll
        for (int j = 0; j < 4; j++) acc[i][j] = 0ull;

    // ring of 8 packed x values: slot (l+i)&7 holds x2[tg + l + i]
    unsigned long long px[8];
    #pragma unroll
    for (int i = 0; i < 8; i++) px[i] = xsu[tg + i];

    const int svbase = p0 >> 2;
    #pragma unroll 1
    for (int lo = 0; lo < L_WIN; lo += 8) {
        #pragma unroll
        for (int li = 0; li < 8; li++) {
            const int l = lo + li;
            float4 sv0 = sT4[l * 16 + svbase];
            float4 sv1 = sT4[l * 16 + svbase + 1];
            union { float4 f; unsigned long long u[2]; } u0, u1;
            u0.f = sv0; u1.f = sv1;
            const unsigned long long sp0 = u0.u[0], sp1 = u0.u[1];
            const unsigned long long sp2 = u1.u[0], sp3 = u1.u[1];
            #pragma unroll
            for (int i = 0; i < 8; i++) {
                const unsigned long long xv = px[(li + i) & 7];
                FMA2(acc[i][0], xv, sp0);
                FMA2(acc[i][1], xv, sp1);
                FMA2(acc[i][2], xv, sp2);
                FMA2(acc[i][3], xv, sp3);
            }
            px[li] = xsu[tg + l + 8];   // refill slot (l&7)==li
        }
    }

    // epilogue: act = exp(2*inv*dot - w2 - s2[p])
    float* outb = out + (size_t)b * T_LEN * P_NUM;
    #pragma unroll
    for (int i = 0; i < 8; i++) {
        const int tl = tg + i;
        const int t  = t_base + tl;
        if (t < TP_LEN) {
            const float inv2 = 2.f * invs[tl];
            const float c    = w2s[tl];
            float r[8];
            #pragma unroll
            for (int j = 0; j < 4; j++) {
                union { unsigned long long u; float2 f; } a; a.u = acc[i][j];
                r[2*j]   = __expf(fmaf(inv2, a.f.x, -(c + s2s[p0 + 2*j])));
                r[2*j+1] = __expf(fmaf(inv2, a.f.y, -(c + s2s[p0 + 2*j + 1])));
            }
            float4* o4 = reinterpret_cast<float4*>(
                outb + (size_t)(t + PAD_LEFT) * P_NUM + p0);
            o4[0] = make_float4(r[0], r[1], r[2], r[3]);
            o4[1] = make_float4(r[4], r[5], r[6], r[7]);
        }
    }
}

extern "C" void kernel_launch(void* const* d_in, const int* in_sizes, int n_in,
                              void* d_out, int out_size) {
    const float* x  = (const float*)d_in[0];   // (32, 8192, 1)
    const float* sh = (const float*)d_in[1];   // (64, 1, 64)
    float* out = (float*)d_out;                // (32, 8192, 64)

    prep_shapelets<<<1, 64>>>(sh);
    pad_zero<<<(BS * 63 * P_NUM + 255) / 256, 256>>>(out);

    dim3 grid((TP_LEN + TILE_T - 1) / TILE_T, BS);   // (32, 32)
    shapelet_kernel<<<grid, 256>>>(x, out);
}